// round 1
// baseline (speedup 1.0000x reference)
#include <cuda_runtime.h>
#include <cstdint>

#define BB   8
#define SS   4096
#define HIDD 1024
#define HH   16
#define DHH  64

#define K1_CHUNKS   128              // chunks per batch
#define ROWS_PER    32               // rows per block (S / K1_CHUNKS)
#define K1_BLOCKS   (BB * K1_CHUNKS) // 1024

// ---------- static scratch (no allocations allowed) ----------
__device__ float g_scratch[(size_t)K1_BLOCKS * HH * HIDD]; // 64 MB  per-block g partials
__device__ float hbar_scratch[(size_t)K1_BLOCKS * HIDD];   // 4 MB   per-block hbar partials
__device__ float wqk_eff[2 * HH * HIDD];                   // 128 KB effective q/k weights
__device__ float qs_buf[(size_t)BB * SS * HH];             // 2 MB   q_scores [b][s][h]
__device__ float hbar_final[BB * HIDD];
__device__ float kv_buf[BB * HH * DHH];
__device__ float mv_buf[BB * HH * DHH];
__device__ float invlen_buf[BB];

typedef unsigned long long u64;

__device__ __forceinline__ u64 ffma2(u64 a, u64 b, u64 c) {
    u64 d;
    asm("fma.rn.f32x2 %0, %1, %2, %3;" : "=l"(d) : "l"(a), "l"(b), "l"(c));
    return d;
}
__device__ __forceinline__ u64 pack2(float x, float y) {
    u64 r; asm("mov.b64 %0, {%1,%2};" : "=l"(r) : "f"(x), "f"(y)); return r;
}
__device__ __forceinline__ float2 unpack2(u64 v) {
    float2 r; asm("mov.b64 {%0,%1}, %2;" : "=f"(r.x), "=f"(r.y) : "l"(v)); return r;
}

// ============================================================
// K0: wqk_eff[ch][h][e] = sum_d aw[h][d] * W[(h*64+d)][e]
// grid 32 (ch*16+h), block 256
// ============================================================
__global__ void k0_weff(const float* __restrict__ Wq,
                        const float* __restrict__ Wk,
                        const float* __restrict__ aw) {
    int ch = blockIdx.x >> 4, h = blockIdx.x & 15;
    const float* W = ch ? Wk : Wq;
    __shared__ float a_sh[DHH];
    if (threadIdx.x < DHH) a_sh[threadIdx.x] = aw[h * DHH + threadIdx.x];
    __syncthreads();
    for (int e = threadIdx.x; e < HIDD; e += blockDim.x) {
        float acc = 0.f;
#pragma unroll 8
        for (int d = 0; d < DHH; d++)
            acc += a_sh[d] * W[(size_t)(h * DHH + d) * HIDD + e];
        wqk_eff[(ch * HH + h) * HIDD + e] = acc;
    }
}

// ============================================================
// K1: single pass over hidden.
// Per block: (b, 32 rows). 8 warps; warp w owns heads h0=2w, h1=2w+1 for
// q-dot, k-dot, and g accumulation. Weights + g live in registers.
// grid 1024, block 256
// ============================================================
__global__ void __launch_bounds__(256, 1)
k1_main(const float* __restrict__ hidden, const float* __restrict__ mask) {
    int blk = blockIdx.x;
    int b = blk >> 7;           // /128
    int chunk = blk & 127;
    int s0 = chunk * ROWS_PER;
    int w = threadIdx.x >> 5, l = threadIdx.x & 31;
    int h0 = 2 * w, h1 = 2 * w + 1;

    // per-lane element range: e = l*32 .. l*32+31, as 16 packed f32x2
    u64 wq0[16], wq1[16], wk0[16], wk1[16];
    {
        const ulonglong2* pq0 = (const ulonglong2*)(wqk_eff + (0 * HH + h0) * HIDD) + l * 8;
        const ulonglong2* pq1 = (const ulonglong2*)(wqk_eff + (0 * HH + h1) * HIDD) + l * 8;
        const ulonglong2* pk0 = (const ulonglong2*)(wqk_eff + (1 * HH + h0) * HIDD) + l * 8;
        const ulonglong2* pk1 = (const ulonglong2*)(wqk_eff + (1 * HH + h1) * HIDD) + l * 8;
#pragma unroll
        for (int i = 0; i < 8; i++) {
            ulonglong2 t;
            t = pq0[i]; wq0[2 * i] = t.x; wq0[2 * i + 1] = t.y;
            t = pq1[i]; wq1[2 * i] = t.x; wq1[2 * i + 1] = t.y;
            t = pk0[i]; wk0[2 * i] = t.x; wk0[2 * i + 1] = t.y;
            t = pk1[i]; wk1[2 * i] = t.x; wk1[2 * i + 1] = t.y;
        }
    }

    u64 g0[16], g1[16];
#pragma unroll
    for (int i = 0; i < 16; i++) { g0[i] = 0ull; g1[i] = 0ull; }
    u64 hb0 = 0ull, hb1 = 0ull;   // hbar chunk: e = w*128 + l*4 .. +3

    const float* rowbase = hidden + ((size_t)b * SS + s0) * HIDD;

    for (int r = 0; r < ROWS_PER; r++) {
        const float* row = rowbase + (size_t)r * HIDD;
        // L2 prefetch two rows ahead (one 128B line per lane = full 4KB row)
        if (r + 2 < ROWS_PER) {
            const char* pf = (const char*)(row + 2 * HIDD) + l * 128;
            asm volatile("prefetch.global.L2 [%0];" :: "l"(pf));
        }
        const ulonglong2* rp = (const ulonglong2*)row + l * 8;
        ulonglong2 rv[8];
#pragma unroll
        for (int i = 0; i < 8; i++) rv[i] = rp[i];

        u64 aq0 = 0ull, aq1 = 0ull, ak0 = 0ull, ak1 = 0ull;
#pragma unroll
        for (int i = 0; i < 8; i++) {
            aq0 = ffma2(rv[i].x, wq0[2 * i], aq0); aq0 = ffma2(rv[i].y, wq0[2 * i + 1], aq0);
            aq1 = ffma2(rv[i].x, wq1[2 * i], aq1); aq1 = ffma2(rv[i].y, wq1[2 * i + 1], aq1);
            ak0 = ffma2(rv[i].x, wk0[2 * i], ak0); ak0 = ffma2(rv[i].y, wk0[2 * i + 1], ak0);
            ak1 = ffma2(rv[i].x, wk1[2 * i], ak1); ak1 = ffma2(rv[i].y, wk1[2 * i + 1], ak1);
        }
        float2 t2;
        t2 = unpack2(aq0); float q0 = t2.x + t2.y;
        t2 = unpack2(aq1); float q1 = t2.x + t2.y;
        t2 = unpack2(ak0); float k0 = t2.x + t2.y;
        t2 = unpack2(ak1); float k1 = t2.x + t2.y;
#pragma unroll
        for (int off = 16; off > 0; off >>= 1) {
            q0 += __shfl_xor_sync(0xffffffffu, q0, off);
            q1 += __shfl_xor_sync(0xffffffffu, q1, off);
            k0 += __shfl_xor_sync(0xffffffffu, k0, off);
            k1 += __shfl_xor_sync(0xffffffffu, k1, off);
        }
        int s = s0 + r;
        float m = __ldg(mask + (size_t)b * SS + s);
        q0 *= m; q1 *= m; k0 *= m; k1 *= m;
        if (l == 0) {
            float2 qq = make_float2(q0, q1);
            *(float2*)(qs_buf + ((size_t)(b * SS + s)) * HH + h0) = qq;
        }
        // g accumulation: g[h] += ks[h] * row (rv still register-resident)
        u64 kk0 = pack2(k0, k0), kk1 = pack2(k1, k1);
#pragma unroll
        for (int i = 0; i < 8; i++) {
            g0[2 * i]     = ffma2(rv[i].x, kk0, g0[2 * i]);
            g0[2 * i + 1] = ffma2(rv[i].y, kk0, g0[2 * i + 1]);
            g1[2 * i]     = ffma2(rv[i].x, kk1, g1[2 * i]);
            g1[2 * i + 1] = ffma2(rv[i].y, kk1, g1[2 * i + 1]);
        }
        // hbar partial: disjoint e = w*128 + l*4
        {
            const ulonglong2 hv = *((const ulonglong2*)(row + w * 128) + l);
            u64 mm = pack2(m, m);
            hb0 = ffma2(hv.x, mm, hb0);
            hb1 = ffma2(hv.y, mm, hb1);
        }
    }

    // write per-block partials (disjoint -> no atomics)
    {
        float* gp0 = g_scratch + ((size_t)blk * HH + h0) * HIDD + l * 32;
        float* gp1 = g_scratch + ((size_t)blk * HH + h1) * HIDD + l * 32;
#pragma unroll
        for (int j = 0; j < 8; j++) {
            float2 a = unpack2(g0[2 * j]), bxy = unpack2(g0[2 * j + 1]);
            ((float4*)gp0)[j] = make_float4(a.x, a.y, bxy.x, bxy.y);
            a = unpack2(g1[2 * j]); bxy = unpack2(g1[2 * j + 1]);
            ((float4*)gp1)[j] = make_float4(a.x, a.y, bxy.x, bxy.y);
        }
        float2 a = unpack2(hb0), bxy = unpack2(hb1);
        *(float4*)(hbar_scratch + (size_t)blk * HIDD + w * 128 + l * 4) =
            make_float4(a.x, a.y, bxy.x, bxy.y);
    }
}

// ============================================================
// K2a: reduce hbar partials per batch + invlen. grid 8, block 1024
// ============================================================
__global__ void k2a_hbar(const float* __restrict__ mask) {
    int b = blockIdx.x;
    int e = threadIdx.x;
    float a0 = 0.f, a1 = 0.f, a2 = 0.f, a3 = 0.f;
    const float* base = hbar_scratch + (size_t)b * K1_CHUNKS * HIDD + e;
    for (int c = 0; c < K1_CHUNKS; c += 4) {
        a0 += base[(size_t)(c + 0) * HIDD];
        a1 += base[(size_t)(c + 1) * HIDD];
        a2 += base[(size_t)(c + 2) * HIDD];
        a3 += base[(size_t)(c + 3) * HIDD];
    }
    hbar_final[b * HIDD + e] = (a0 + a1) + (a2 + a3);

    // invlen = 1 / sum_s mask[b][s]
    __shared__ float red[1024];
    float a = 0.f;
    for (int i = threadIdx.x; i < SS; i += 1024) a += mask[(size_t)b * SS + i];
    red[threadIdx.x] = a;
    __syncthreads();
    for (int st = 512; st > 0; st >>= 1) {
        if (threadIdx.x < st) red[threadIdx.x] += red[threadIdx.x + st];
        __syncthreads();
    }
    if (threadIdx.x == 0) invlen_buf[b] = 1.f / red[0];
}

// ============================================================
// K2: per (b,h): reduce g partials, then kv/mv = (g|hbar) . Wv rows
// grid 128 (b*16+h), block 256 (8 warps x 8 d-outputs)
// ============================================================
__global__ void k2_kvmv(const float* __restrict__ Wv) {
    int b = blockIdx.x >> 4, h = blockIdx.x & 15;
    __shared__ float gsum[HIDD];
    __shared__ float hsum[HIDD];

    for (int e = threadIdx.x; e < HIDD; e += 256) {
        float a0 = 0.f, a1 = 0.f, a2 = 0.f, a3 = 0.f;
        const float* base = g_scratch + (((size_t)b * K1_CHUNKS) * HH + h) * HIDD + e;
        for (int c = 0; c < K1_CHUNKS; c += 4) {
            a0 += base[(size_t)(c + 0) * HH * HIDD];
            a1 += base[(size_t)(c + 1) * HH * HIDD];
            a2 += base[(size_t)(c + 2) * HH * HIDD];
            a3 += base[(size_t)(c + 3) * HH * HIDD];
        }
        gsum[e] = (a0 + a1) + (a2 + a3);
        hsum[e] = hbar_final[b * HIDD + e];
    }
    __syncthreads();

    int w = threadIdx.x >> 5, l = threadIdx.x & 31;
    for (int dd = 0; dd < 8; dd++) {
        int d = w * 8 + dd;
        const float* wvrow = Wv + (size_t)(h * DHH + d) * HIDD;
        float ak = 0.f, am = 0.f;
        for (int e = l; e < HIDD; e += 32) {
            float wv = __ldg(wvrow + e);
            ak += gsum[e] * wv;
            am += hsum[e] * wv;
        }
#pragma unroll
        for (int off = 16; off > 0; off >>= 1) {
            ak += __shfl_xor_sync(0xffffffffu, ak, off);
            am += __shfl_xor_sync(0xffffffffu, am, off);
        }
        if (l == 0) {
            kv_buf[((b * HH + h) << 6) + d] = ak;
            mv_buf[((b * HH + h) << 6) + d] = am;
        }
    }
}

// ============================================================
// K3: out[b][s][h*64+d] = (qs[b,s,h]*mv[b,h,d] + kv[b,h,d]) * invlen[b]
// grid 32768 (one row each), block 256 (float4 per thread)
// ============================================================
__global__ void k3_out(float* __restrict__ out) {
    int row = blockIdx.x;          // b*4096 + s
    int b = row >> 12;
    int t = threadIdx.x;
    int h = t >> 4;                // (t*4)/64
    int d = (t & 15) << 2;
    float qsv = __ldg(qs_buf + (size_t)row * HH + h);
    float4 mv4 = *(const float4*)(mv_buf + ((b * HH + h) << 6) + d);
    float4 kv4 = *(const float4*)(kv_buf + ((b * HH + h) << 6) + d);
    float il = invlen_buf[b];
    float4 o;
    o.x = (qsv * mv4.x + kv4.x) * il;
    o.y = (qsv * mv4.y + kv4.y) * il;
    o.z = (qsv * mv4.z + kv4.z) * il;
    o.w = (qsv * mv4.w + kv4.w) * il;
    ((float4*)out)[(size_t)row * 256 + t] = o;
}

// ============================================================
extern "C" void kernel_launch(void* const* d_in, const int* in_sizes, int n_in,
                              void* d_out, int out_size) {
    const float* hidden = (const float*)d_in[0];
    const float* mask   = (const float*)d_in[1];
    const float* Wq     = (const float*)d_in[2];
    const float* Wk     = (const float*)d_in[3];
    const float* Wv     = (const float*)d_in[4];
    const float* aw     = (const float*)d_in[5];
    float* out = (float*)d_out;

    k0_weff<<<32, 256>>>(Wq, Wk, aw);
    k1_main<<<K1_BLOCKS, 256>>>(hidden, mask);
    k2a_hbar<<<BB, 1024>>>(mask);
    k2_kvmv<<<BB * HH, 256>>>(Wv);
    k3_out<<<BB * SS, 256>>>(out);
}